// round 4
// baseline (speedup 1.0000x reference)
#include <cuda_runtime.h>
#include <math.h>

#define B 8
#define N 4096
#define DF 768
#define K1 8
#define K2 2
#define DS 128
#define BK (B*K1)        // 64
#define NS (BK*K2)       // 128 slot rows
#define SCALE 0.088388347648318447f
#define EPS_SA 1e-8f
#define OBJ_SIZE (NS*DS)

// ------------------- scratch (device globals) -------------------
__device__ float g_mean[B*N];
__device__ float g_var[B*N];
__device__ float g_denom[BK];
__device__ float g_s[BK*N];
__device__ float g_sm[BK];                       // sum_j s_j * m_j per bk
__device__ __align__(16) float g_T[BK*DF];       // sum_j s_j * x_j per bk
__device__ float g_slots[NS*DS];
__device__ __align__(16) float g_aD[BK*DF];      // delta a-vector per bk
__device__ float g_sAD[BK];
__device__ float g_beD[BK];
__device__ float g_acc0[BK*DF];                  // slot-0 accumulator
__device__ float g_z0[BK];
__device__ float g_d0[BK];
__device__ float g_cv[DS];
// transposed weights
__device__ float g_WqT[DS*DS];
__device__ float g_WvT[DF*DS];
__device__ float g_WihT[DS*3*DS];
__device__ float g_WhhT[DS*3*DS];
__device__ float g_W1T[DS*4*DS];
__device__ float g_W2T[4*DS*DS];

// paired warp reduction: on exit all lanes hold x=sum(x), y=sum(y). 8 SHFLs.
__device__ __forceinline__ void warp_reduce2(float& x, float& y, int lane) {
    float xo = __shfl_xor_sync(0xffffffffu, x, 16);
    float yo = __shfl_xor_sync(0xffffffffu, y, 16);
    float v  = (lane < 16) ? (x + xo) : (y + yo);
    #pragma unroll
    for (int off = 8; off; off >>= 1) v += __shfl_xor_sync(0xffffffffu, v, off);
    x = __shfl_sync(0xffffffffu, v, 0);
    y = __shfl_sync(0xffffffffu, v, 16);
}

__device__ __forceinline__ float block_reduce_256(float v, float* red, int tid) {
    red[tid] = v; __syncthreads();
    #pragma unroll
    for (int h = 128; h > 0; h >>= 1) {
        if (tid < h) red[tid] += red[tid + h];
        __syncthreads();
    }
    float r = red[0];
    __syncthreads();
    return r;
}

// ------------------- one-time kernels -------------------
__global__ void tr_kernel(const float* __restrict__ Wq, const float* __restrict__ Wv,
                          const float* __restrict__ Wih, const float* __restrict__ Whh,
                          const float* __restrict__ W1, const float* __restrict__ W2) {
    int i = blockIdx.x*256 + threadIdx.x;
    if (i < DS*DS) { int f = i/DS, o = i%DS; g_WqT[i] = Wq[o*DS + f]; return; }
    i -= DS*DS;
    if (i < DF*DS) { int f = i/DS, o = i%DS; g_WvT[i] = Wv[o*DF + f]; return; }
    i -= DF*DS;
    if (i < DS*3*DS) { int f = i/(3*DS), o = i%(3*DS); g_WihT[i] = Wih[o*DS + f]; return; }
    i -= DS*3*DS;
    if (i < DS*3*DS) { int f = i/(3*DS), o = i%(3*DS); g_WhhT[i] = Whh[o*DS + f]; return; }
    i -= DS*3*DS;
    if (i < DS*4*DS) { int f = i/(4*DS), o = i%(4*DS); g_W1T[i] = W1[o*DS + f]; return; }
    i -= DS*4*DS;
    if (i < 4*DS*DS) { int o = i/DS, t = i%DS; g_W2T[i] = W2[t*4*DS + o]; return; }
}

// per-token mean/var over DF.  grid B*N/8 blocks of 256 (warp/row)
__global__ void stats_kernel(const float* __restrict__ tokens) {
    int row  = blockIdx.x * 8 + (threadIdx.x >> 5);
    int lane = threadIdx.x & 31;
    const float4* xp = (const float4*)(tokens + (size_t)row * DF);
    float s = 0.f, s2 = 0.f;
    #pragma unroll
    for (int k = 0; k < 6; k++) {
        float4 v = xp[k*32 + lane];
        s  += v.x + v.y + v.z + v.w;
        s2 += v.x*v.x + v.y*v.y + v.z*v.z + v.w*v.w;
    }
    #pragma unroll
    for (int off = 16; off; off >>= 1) {
        s  += __shfl_xor_sync(0xffffffffu, s,  off);
        s2 += __shfl_xor_sync(0xffffffffu, s2, off);
    }
    if (lane == 0) {
        float m = s * (1.f/DF);
        g_mean[row] = m;
        g_var[row]  = s2 * (1.f/DF) - m*m;
    }
}

__global__ void denom_kernel(const float* __restrict__ masks) {
    __shared__ float red[256];
    int bk = blockIdx.x, tid = threadIdx.x;
    float s = 0.f;
    for (int j = tid; j < N; j += 256) s += masks[(size_t)bk*N + j];
    float tot = block_reduce_256(s, red, tid);
    if (tid == 0) g_denom[bk] = tot * (1.f/N);
}

__global__ void s_kernel(const float* __restrict__ masks) {
    int idx = blockIdx.x*256 + threadIdx.x;
    if (idx >= BK*N) return;
    int bk = idx / N;
    int b  = bk / K1;
    int j  = idx - bk*N;
    float denom = g_denom[bk];
    float w = (denom > 1e-6f) ? (masks[idx] / (denom + 1e-6f)) : 1.0f;
    float v = g_var[b*N + j];
    g_s[idx] = w * rsqrtf(w*w*v + 1e-5f);
}

// T[bk][f] = sum_j s[bk][j] * x[b][j][f].  grid = 8 b * 24 fchunks, 256 thr (32 f x 8 jg)
__global__ void t_kernel(const float* __restrict__ tokens) {
    __shared__ float Tsh[8*32];
    int b  = blockIdx.x / 24;
    int fc = blockIdx.x % 24;
    int fl = threadIdx.x & 31, jg = threadIdx.x >> 5;
    int f  = fc*32 + fl;
    float acc[8] = {0,0,0,0,0,0,0,0};
    int j0 = jg*512;
    for (int j = j0; j < j0 + 512; j++) {
        float x = tokens[(size_t)(b*N + j)*DF + f];
        #pragma unroll
        for (int u = 0; u < 8; u++) acc[u] += g_s[(size_t)(b*8 + u)*N + j] * x;
    }
    Tsh[threadIdx.x] = 0.f;
    __syncthreads();
    #pragma unroll
    for (int u = 0; u < 8; u++) atomicAdd(&Tsh[u*32 + fl], acc[u]);
    __syncthreads();
    int u = threadIdx.x >> 5, fl2 = threadIdx.x & 31;
    g_T[(size_t)(b*8 + u)*DF + fc*32 + fl2] = Tsh[threadIdx.x];
}

// SM[bk] = sum_j s[bk][j]*mean[b][j]
__global__ void sm_kernel() {
    __shared__ float red[256];
    int bk = blockIdx.x, b = bk >> 3, tid = threadIdx.x;
    float s = 0.f;
    for (int j = tid; j < N; j += 256) s += g_s[(size_t)bk*N + j] * g_mean[b*N + j];
    float tot = block_reduce_256(s, red, tid);
    if (tid == 0) g_sm[bk] = tot;
}

__global__ void slots_init_kernel(const float* __restrict__ ps, const float* __restrict__ eps) {
    int idx = blockIdx.x*256 + threadIdx.x;
    if (idx >= NS*DS) return;
    int r = idx / DS, d = idx - r*DS;
    int bk = r >> 1;
    g_slots[idx] = ps[bk*DS + d] + 0.01f * eps[idx];
}

// cv = Wv @ ln_in_b  (coalesced via WvT)
__global__ void cv_kernel(const float* __restrict__ lnb) {
    int t = threadIdx.x;
    float acc = 0.f;
    #pragma unroll 8
    for (int f = 0; f < DF; f++) acc += g_WvT[f*DS + t] * lnb[f];
    g_cv[t] = acc;
}

// ------------------- per-iteration kernels -------------------
// per bk: LN both slots, q0,q1, qDelta, aDelta = g.*(Wk^T qD), sums; zero accumulators.
__global__ void qa_kernel(const float* __restrict__ Wk,
                          const float* __restrict__ sg, const float* __restrict__ sb,
                          const float* __restrict__ ig, const float* __restrict__ ib) {
    __shared__ float sn[2][DS], qsh[2][DS], qD[DS], red[256];
    int bk = blockIdx.x, tid = threadIdx.x;
    int half = tid >> 7, t = tid & 127;
    int r = bk*2 + half;
    float val = g_slots[r*DS + t];
    // segmented mean
    red[tid] = val; __syncthreads();
    #pragma unroll
    for (int h = 64; h; h >>= 1) { if (t < h) red[tid] += red[tid + h]; __syncthreads(); }
    float m = red[half*128] * (1.f/DS);
    __syncthreads();
    float dv = val - m;
    red[tid] = dv*dv; __syncthreads();
    #pragma unroll
    for (int h = 64; h; h >>= 1) { if (t < h) red[tid] += red[tid + h]; __syncthreads(); }
    float rstd = rsqrtf(red[half*128] * (1.f/DS) + 1e-5f);
    __syncthreads();
    sn[half][t] = dv * rstd * sg[t] + sb[t];
    __syncthreads();
    float q = 0.f;
    #pragma unroll 8
    for (int f = 0; f < DS; f++) q += g_WqT[f*DS + t] * sn[half][f];
    qsh[half][t] = q;
    __syncthreads();
    if (tid < DS) qD[tid] = qsh[0][tid] - qsh[1][tid];
    __syncthreads();
    float psum = 0.f, pbeta = 0.f;
    #pragma unroll
    for (int ff = 0; ff < 3; ff++) {
        int f = ff*256 + tid;
        float raw = 0.f;
        #pragma unroll 8
        for (int c = 0; c < DS; c++) raw += Wk[c*DF + f] * qD[c];
        float a = raw * ig[f];
        g_aD[(size_t)bk*DF + f] = a;
        g_acc0[(size_t)bk*DF + f] = 0.f;     // zero accumulator for big pass
        psum  += a;
        pbeta += raw * ib[f];
    }
    float tsum  = block_reduce_256(psum, red, tid);
    float tbeta = block_reduce_256(pbeta, red, tid);
    if (tid == 0) { g_sAD[bk] = tsum; g_beD[bk] = tbeta; g_z0[bk] = 0.f; g_d0[bk] = 0.f; }
}

// Fused delta-dot -> sigmoid -> slot-0 accumulation for a PAIR of bks sharing tokens.
// grid = 32 tiles * 32 pairs, block 128 (4 warps x 32 tokens).
__global__ void __launch_bounds__(128) big_kernel(const float* __restrict__ tokens,
                                                  const float* __restrict__ masks,
                                                  float* __restrict__ out, int last) {
    int p    = blockIdx.x & 31;
    int tile = blockIdx.x >> 5;
    int bk0  = 2*p, bk1 = bk0 + 1;
    int b    = p >> 2;
    int w    = threadIdx.x >> 5, lane = threadIdx.x & 31;

    const float4* a0p = (const float4*)(g_aD + (size_t)bk0*DF);
    const float4* a1p = (const float4*)(g_aD + (size_t)bk1*DF);
    float4 a0[6], a1[6], ac0[6], ac1[6];
    #pragma unroll
    for (int k = 0; k < 6; k++) {
        a0[k] = a0p[k*32 + lane];
        a1[k] = a1p[k*32 + lane];
        ac0[k] = make_float4(0.f,0.f,0.f,0.f);
        ac1[k] = make_float4(0.f,0.f,0.f,0.f);
    }
    float sA0 = g_sAD[bk0], sA1 = g_sAD[bk1];
    float be0 = g_beD[bk0], be1 = g_beD[bk1];
    float z0 = 0.f, z1 = 0.f, dd0 = 0.f, dd1 = 0.f;
    float k00 = 0.f, k10 = 0.f;
    int j0 = tile*128 + w*32;

    for (int t = 0; t < 32; t++) {
        int j = j0 + t;
        const float4* xp = (const float4*)(tokens + (size_t)(b*N + j)*DF);
        float4 xv[6];
        #pragma unroll
        for (int k = 0; k < 6; k++) xv[k] = xp[k*32 + lane];
        float dt0 = 0.f, dt1 = 0.f;
        #pragma unroll
        for (int k = 0; k < 6; k++) {
            dt0 += a0[k].x*xv[k].x + a0[k].y*xv[k].y + a0[k].z*xv[k].z + a0[k].w*xv[k].w;
            dt1 += a1[k].x*xv[k].x + a1[k].y*xv[k].y + a1[k].z*xv[k].z + a1[k].w*xv[k].w;
        }
        warp_reduce2(dt0, dt1, lane);
        float s0 = g_s[(size_t)bk0*N + j], s1 = g_s[(size_t)bk1*N + j];
        float m  = g_mean[b*N + j];
        float q0 = SCALE * (s0*(dt0 - m*sA0) + be0);
        float q1 = SCALE * (s1*(dt1 - m*sA1) + be1);
        float p0 = 1.f / (1.f + __expf(-q0));
        float p1 = 1.f / (1.f + __expf(-q1));
        if (t == lane) { k00 = p0; k10 = p1; }
        float at0 = p0 + EPS_SA, at1 = p1 + EPS_SA;
        float c0 = at0*s0, c1 = at1*s1;
        z0 += at0; z1 += at1; dd0 += c0*m; dd1 += c1*m;
        #pragma unroll
        for (int k = 0; k < 6; k++) {
            ac0[k].x += c0*xv[k].x; ac0[k].y += c0*xv[k].y;
            ac0[k].z += c0*xv[k].z; ac0[k].w += c0*xv[k].w;
            ac1[k].x += c1*xv[k].x; ac1[k].y += c1*xv[k].y;
            ac1[k].z += c1*xv[k].z; ac1[k].w += c1*xv[k].w;
        }
    }

    if (last) {   // child_gating for both slots of both bks (final-iter attention)
        int j = j0 + lane;
        float mk0 = masks[(size_t)bk0*N + j];
        float mk1 = masks[(size_t)bk1*N + j];
        out[OBJ_SIZE + (size_t)(bk0*2)*N + j]     = (k00 + EPS_SA) * mk0;
        out[OBJ_SIZE + (size_t)(bk0*2+1)*N + j]   = (1.f - k00 + EPS_SA) * mk0;
        out[OBJ_SIZE + (size_t)(bk1*2)*N + j]     = (k10 + EPS_SA) * mk1;
        out[OBJ_SIZE + (size_t)(bk1*2+1)*N + j]   = (1.f - k10 + EPS_SA) * mk1;
    }

    __shared__ float shA[2*DF];
    for (int i = threadIdx.x; i < 2*DF; i += 128) shA[i] = 0.f;
    __syncthreads();
    #pragma unroll
    for (int k = 0; k < 6; k++) {
        int f = (k*32 + lane)*4;
        atomicAdd(&shA[f],      ac0[k].x); atomicAdd(&shA[f+1],    ac0[k].y);
        atomicAdd(&shA[f+2],    ac0[k].z); atomicAdd(&shA[f+3],    ac0[k].w);
        atomicAdd(&shA[DF+f],   ac1[k].x); atomicAdd(&shA[DF+f+1], ac1[k].y);
        atomicAdd(&shA[DF+f+2], ac1[k].z); atomicAdd(&shA[DF+f+3], ac1[k].w);
    }
    __syncthreads();
    for (int i = threadIdx.x; i < DF; i += 128) {
        atomicAdd(&g_acc0[(size_t)bk0*DF + i], shA[i]);
        atomicAdd(&g_acc0[(size_t)bk1*DF + i], shA[DF + i]);
    }
    if (lane == 0) {
        atomicAdd(&g_z0[bk0], z0); atomicAdd(&g_z0[bk1], z1);
        atomicAdd(&g_d0[bk0], dd0); atomicAdd(&g_d0[bk1], dd1);
    }
}

// per slot row: reconstruct A/D/Z, updates = WvT(g*(A-D))/Z + cv -> GRU -> LN -> MLP.
__global__ void upd_kernel(const float* __restrict__ ig,
                           const float* __restrict__ bih, const float* __restrict__ bhh,
                           const float* __restrict__ mg,  const float* __restrict__ mb,
                           const float* __restrict__ b1,  const float* __restrict__ b2,
                           float* __restrict__ out, int last) {
    __shared__ float gv[DF];
    __shared__ float su[DS], sh[DS], shh[DS];
    __shared__ float sy[4*DS];
    __shared__ float red[DS];
    int r = blockIdx.x, t = threadIdx.x;
    int bk = r >> 1, i = r & 1;
    const float ONE = 1.f + 2.f*EPS_SA;
    float Z0 = g_z0[bk], D0 = g_d0[bk];
    float Z = i ? (4096.f*ONE - Z0) : Z0;
    float D = i ? (g_sm[bk]*ONE - D0) : D0;
    for (int f = t; f < DF; f += DS) {
        float A = g_acc0[(size_t)bk*DF + f];
        if (i) A = g_T[(size_t)bk*DF + f]*ONE - A;
        gv[f] = ig[f] * (A - D);
    }
    float hprev = g_slots[r*DS + t];
    sh[t] = hprev;
    __syncthreads();
    float acc = 0.f;
    #pragma unroll 8
    for (int f = 0; f < DF; f++) acc += g_WvT[f*DS + t] * gv[f];
    su[t] = acc / Z + g_cv[t];
    __syncthreads();
    // GRU (coalesced transposed weights)
    float gi0 = bih[t], gi1 = bih[DS+t], gi2 = bih[2*DS+t];
    float gh0 = bhh[t], gh1 = bhh[DS+t], gh2 = bhh[2*DS+t];
    #pragma unroll 4
    for (int f = 0; f < DS; f++) {
        float uf = su[f], hf = sh[f];
        gi0 += g_WihT[f*(3*DS) + t]*uf;
        gi1 += g_WihT[f*(3*DS) + DS + t]*uf;
        gi2 += g_WihT[f*(3*DS) + 2*DS + t]*uf;
        gh0 += g_WhhT[f*(3*DS) + t]*hf;
        gh1 += g_WhhT[f*(3*DS) + DS + t]*hf;
        gh2 += g_WhhT[f*(3*DS) + 2*DS + t]*hf;
    }
    float rr = 1.f / (1.f + __expf(-(gi0 + gh0)));
    float zz = 1.f / (1.f + __expf(-(gi1 + gh1)));
    float nn = tanhf(gi2 + rr*gh2);
    float news = (1.f - zz)*nn + zz*hprev;
    // LN over 128 lanes
    red[t] = news; __syncthreads();
    #pragma unroll
    for (int h2 = 64; h2; h2 >>= 1) { if (t < h2) red[t] += red[t+h2]; __syncthreads(); }
    float m = red[0] * (1.f/DS); __syncthreads();
    float dv = news - m;
    red[t] = dv*dv; __syncthreads();
    #pragma unroll
    for (int h2 = 64; h2; h2 >>= 1) { if (t < h2) red[t] += red[t+h2]; __syncthreads(); }
    float rstd = rsqrtf(red[0]*(1.f/DS) + 1e-5f); __syncthreads();
    shh[t] = dv*rstd*mg[t] + mb[t];
    __syncthreads();
    // MLP: gelu(h@W1^T+b1)@W2^T+b2 (exact gelu), coalesced transposed weights
    #pragma unroll
    for (int oo = 0; oo < 4; oo++) {
        int o = oo*DS + t;
        float a2 = b1[o];
        #pragma unroll 4
        for (int f = 0; f < DS; f++) a2 += g_W1T[f*(4*DS) + o]*shh[f];
        sy[o] = 0.5f * a2 * (1.f + erff(a2 * 0.70710678118654752f));
    }
    __syncthreads();
    float o2 = b2[t];
    #pragma unroll 8
    for (int o = 0; o < 4*DS; o++) o2 += g_W2T[o*DS + t]*sy[o];
    g_slots[r*DS + t] = o2;
    if (last) out[r*DS + t] = o2;
}

// ------------------- launch -------------------
extern "C" void kernel_launch(void* const* d_in, const int* in_sizes, int n_in,
                              void* d_out, int out_size) {
    const float* tokens = (const float*)d_in[0];
    const float* pslots = (const float*)d_in[1];
    const float* masks  = (const float*)d_in[2];
    const float* eps    = (const float*)d_in[3];
    const float* ig     = (const float*)d_in[4];
    const float* ib     = (const float*)d_in[5];
    const float* sg     = (const float*)d_in[6];
    const float* sb     = (const float*)d_in[7];
    const float* Wq     = (const float*)d_in[8];
    const float* Wk     = (const float*)d_in[9];
    const float* Wv     = (const float*)d_in[10];
    const float* Wih    = (const float*)d_in[11];
    const float* Whh    = (const float*)d_in[12];
    const float* bih    = (const float*)d_in[13];
    const float* bhh    = (const float*)d_in[14];
    const float* mg     = (const float*)d_in[15];
    const float* mb     = (const float*)d_in[16];
    const float* W1     = (const float*)d_in[17];
    const float* b1     = (const float*)d_in[18];
    const float* W2     = (const float*)d_in[19];
    const float* b2     = (const float*)d_in[20];
    float* out = (float*)d_out;

    tr_kernel<<<(DS*DS + DF*DS + 2*DS*3*DS + 2*DS*4*DS + 255)/256, 256>>>(Wq, Wv, Wih, Whh, W1, W2);
    stats_kernel<<<B*N/8, 256>>>(tokens);
    denom_kernel<<<BK, 256>>>(masks);
    s_kernel<<<(BK*N + 255)/256, 256>>>(masks);
    t_kernel<<<B*24, 256>>>(tokens);
    sm_kernel<<<BK, 256>>>();
    slots_init_kernel<<<(NS*DS + 255)/256, 256>>>(pslots, eps);
    cv_kernel<<<1, DS>>>(ib);

    for (int it = 0; it < 3; it++) {
        int last = (it == 2);
        qa_kernel<<<BK, 256>>>(Wk, sg, sb, ig, ib);
        big_kernel<<<32*32, 128>>>(tokens, masks, out, last);
        upd_kernel<<<NS, DS>>>(ig, bih, bhh, mg, mb, b1, b2, out, last);
    }
}

// round 8
// speedup vs baseline: 1.2026x; 1.2026x over previous
#include <cuda_runtime.h>
#include <math.h>

#define B 8
#define N 4096
#define DF 768
#define K1 8
#define K2 2
#define DS 128
#define BK (B*K1)        // 64
#define NS (BK*K2)       // 128 slot rows
#define SCALE 0.088388347648318447f
#define EPS_SA 1e-8f
#define OBJ_SIZE (NS*DS)

// ------------------- scratch (device globals) -------------------
__device__ float g_mean[B*N];
__device__ float g_var[B*N];
__device__ float g_s[BK*N];
__device__ float g_sm[BK];                       // sum_j s_j * m_j per bk
__device__ __align__(16) float g_T[BK*DF];       // sum_j s_j * x_j per bk
__device__ float g_slots[NS*DS];
__device__ __align__(16) float g_aD[BK*DF];      // delta a-vector per bk
__device__ float g_sAD[BK];
__device__ float g_beD[BK];
__device__ __align__(16) float g_acc0[BK*DF];    // slot-0 accumulator
__device__ float g_z0[BK];
__device__ float g_d0[BK];
__device__ float g_cv[DS];
// transposed weights
__device__ float g_WvT[DF*DS];
__device__ float g_WihT[DS*3*DS];
__device__ float g_WhhT[DS*3*DS];
__device__ float g_W1T[DS*4*DS];
__device__ float g_W2T[4*DS*DS];

// paired warp reduction: on exit all lanes hold x=sum(x), y=sum(y).
__device__ __forceinline__ void warp_reduce2(float& x, float& y, int lane) {
    float xo = __shfl_xor_sync(0xffffffffu, x, 16);
    float yo = __shfl_xor_sync(0xffffffffu, y, 16);
    float v  = (lane < 16) ? (x + xo) : (y + yo);
    #pragma unroll
    for (int off = 8; off; off >>= 1) v += __shfl_xor_sync(0xffffffffu, v, off);
    x = __shfl_sync(0xffffffffu, v, 0);
    y = __shfl_sync(0xffffffffu, v, 16);
}

__device__ __forceinline__ float block_reduce_256(float v, float* red, int tid) {
    red[tid] = v; __syncthreads();
    #pragma unroll
    for (int h = 128; h > 0; h >>= 1) {
        if (tid < h) red[tid] += red[tid + h];
        __syncthreads();
    }
    float r = red[0];
    __syncthreads();
    return r;
}

// ------------------- one-time kernels -------------------
// per-token mean/var over DF.  grid B*N/8 blocks of 256 (warp/row)
__global__ void stats_kernel(const float* __restrict__ tokens) {
    int row  = blockIdx.x * 8 + (threadIdx.x >> 5);
    int lane = threadIdx.x & 31;
    const float4* xp = (const float4*)(tokens + (size_t)row * DF);
    float s = 0.f, s2 = 0.f;
    #pragma unroll
    for (int k = 0; k < 6; k++) {
        float4 v = xp[k*32 + lane];
        s  += v.x + v.y + v.z + v.w;
        s2 += v.x*v.x + v.y*v.y + v.z*v.z + v.w*v.w;
    }
    #pragma unroll
    for (int off = 16; off; off >>= 1) {
        s  += __shfl_xor_sync(0xffffffffu, s,  off);
        s2 += __shfl_xor_sync(0xffffffffu, s2, off);
    }
    if (lane == 0) {
        float m = s * (1.f/DF);
        g_mean[row] = m;
        g_var[row]  = s2 * (1.f/DF) - m*m;
    }
}

// fused denom + s.  grid BK blocks of 256
__global__ void dss_kernel(const float* __restrict__ masks) {
    __shared__ float red[256];
    int bk = blockIdx.x, b = bk >> 3, tid = threadIdx.x;
    float s = 0.f;
    for (int j = tid; j < N; j += 256) s += masks[(size_t)bk*N + j];
    float denom = block_reduce_256(s, red, tid) * (1.f/N);
    int good = denom > 1e-6f;
    float inv = 1.f / (denom + 1e-6f);
    for (int j = tid; j < N; j += 256) {
        float w = good ? masks[(size_t)bk*N + j] * inv : 1.0f;
        float v = g_var[b*N + j];
        g_s[(size_t)bk*N + j] = w * rsqrtf(w*w*v + 1e-5f);
    }
}

// transpose weight matrices (Wv, Wih, Whh, W1, W2)
__global__ void tr_kernel(const float* __restrict__ Wv,
                          const float* __restrict__ Wih, const float* __restrict__ Whh,
                          const float* __restrict__ W1, const float* __restrict__ W2) {
    int i = blockIdx.x*256 + threadIdx.x;
    if (i < DF*DS) { int f = i/DS, o = i%DS; g_WvT[i] = Wv[o*DF + f]; return; }
    i -= DF*DS;
    if (i < DS*3*DS) { int f = i/(3*DS), o = i%(3*DS); g_WihT[i] = Wih[o*DS + f]; return; }
    i -= DS*3*DS;
    if (i < DS*3*DS) { int f = i/(3*DS), o = i%(3*DS); g_WhhT[i] = Whh[o*DS + f]; return; }
    i -= DS*3*DS;
    if (i < DS*4*DS) { int f = i/(4*DS), o = i%(4*DS); g_W1T[i] = W1[o*DS + f]; return; }
    i -= DS*4*DS;
    if (i < 4*DS*DS) { int o = i/DS, t = i%DS; g_W2T[i] = W2[t*4*DS + o]; return; }
}

// cv = Wv @ ln_in_b (coalesced via WvT, 4 accumulators)
__global__ void cv_kernel(const float* __restrict__ lnb) {
    int t = threadIdx.x;
    float a0=0.f,a1=0.f,a2=0.f,a3=0.f;
    #pragma unroll 4
    for (int f = 0; f < DF; f += 4) {
        a0 += g_WvT[(f+0)*DS + t] * lnb[f+0];
        a1 += g_WvT[(f+1)*DS + t] * lnb[f+1];
        a2 += g_WvT[(f+2)*DS + t] * lnb[f+2];
        a3 += g_WvT[(f+3)*DS + t] * lnb[f+3];
    }
    g_cv[t] = (a0+a1)+(a2+a3);
}

// ------------------- per-iteration kernels -------------------
// per bk: (opt) init slots, LN both slots, qDelta, aDelta; zero accumulators.
__global__ void qa_kernel(const float* __restrict__ ps, const float* __restrict__ eps,
                          const float* __restrict__ Wq, const float* __restrict__ Wk,
                          const float* __restrict__ sg, const float* __restrict__ sb,
                          const float* __restrict__ ig, const float* __restrict__ ib,
                          int first) {
    __shared__ float sn[2][DS], qsh[2][DS], qD[DS], red[256];
    int bk = blockIdx.x, tid = threadIdx.x;
    int half = tid >> 7, t = tid & 127;
    int r = bk*2 + half;
    float val;
    if (first) {
        val = ps[bk*DS + t] + 0.01f * eps[r*DS + t];
        g_slots[r*DS + t] = val;
    } else {
        val = g_slots[r*DS + t];
    }
    // segmented mean/var per half
    red[tid] = val; __syncthreads();
    #pragma unroll
    for (int h = 64; h; h >>= 1) { if (t < h) red[tid] += red[tid + h]; __syncthreads(); }
    float m = red[half*128] * (1.f/DS);
    __syncthreads();
    float dv = val - m;
    red[tid] = dv*dv; __syncthreads();
    #pragma unroll
    for (int h = 64; h; h >>= 1) { if (t < h) red[tid] += red[tid + h]; __syncthreads(); }
    float rstd = rsqrtf(red[half*128] * (1.f/DS) + 1e-5f);
    __syncthreads();
    sn[half][t] = dv * rstd * sg[t] + sb[t];
    __syncthreads();
    {   // q = sn @ Wq^T  (Wq row-major, small, L2-resident)
        float q0 = 0.f, q1 = 0.f;
        #pragma unroll 4
        for (int f = 0; f < DS; f += 2) {
            q0 += Wq[t*DS + f]   * sn[half][f];
            q1 += Wq[t*DS + f+1] * sn[half][f+1];
        }
        qsh[half][t] = q0 + q1;
    }
    __syncthreads();
    if (tid < DS) qD[tid] = qsh[0][tid] - qsh[1][tid];
    __syncthreads();
    float psum = 0.f, pbeta = 0.f;
    #pragma unroll
    for (int ff = 0; ff < 3; ff++) {
        int f = ff*256 + tid;
        float r0 = 0.f, r1 = 0.f;
        #pragma unroll 4
        for (int c = 0; c < DS; c += 2) {
            r0 += Wk[c*DF + f]     * qD[c];
            r1 += Wk[(c+1)*DF + f] * qD[c+1];
        }
        float raw = r0 + r1;
        float a = raw * ig[f];
        g_aD[(size_t)bk*DF + f]   = a;
        g_acc0[(size_t)bk*DF + f] = 0.f;
        if (first) g_T[(size_t)bk*DF + f] = 0.f;
        psum  += a;
        pbeta += raw * ib[f];
    }
    float tsum  = block_reduce_256(psum, red, tid);
    float tbeta = block_reduce_256(pbeta, red, tid);
    if (tid == 0) {
        g_sAD[bk] = tsum; g_beD[bk] = tbeta;
        g_z0[bk] = 0.f; g_d0[bk] = 0.f;
        if (first) g_sm[bk] = 0.f;
    }
}

// Phased big kernel: block = 256 thr, pair of bks, 128 tokens in 4 chunks of 32.
// smem: xs[32][193] float4 (stride 772 floats), aD0/aD1[192] float4, dt partials.
__global__ void __launch_bounds__(256) big_kernel(const float* __restrict__ tokens,
                                                  const float* __restrict__ masks,
                                                  float* __restrict__ out,
                                                  int first, int last) {
    extern __shared__ float4 sm4[];
    float4* xs  = sm4;            // 6176 float4
    float4* a0s = sm4 + 6176;     // 192
    float4* a1s = sm4 + 6368;     // 192
    float*  dtp = (float*)(sm4 + 6560);  // 512 floats

    int p = blockIdx.x & 31, tile = blockIdx.x >> 5;
    int bk0 = 2*p, bk1 = bk0 + 1, b = p >> 2;
    int tid = threadIdx.x, w = tid >> 5, lane = tid & 31;

    if (tid < 192) {
        a0s[tid] = ((const float4*)(g_aD + (size_t)bk0*DF))[tid];
        a1s[tid] = ((const float4*)(g_aD + (size_t)bk1*DF))[tid];
    }
    float sA0 = g_sAD[bk0], sA1 = g_sAD[bk1];
    float be0 = g_beD[bk0], be1 = g_beD[bk1];
    float4 acc0 = {0,0,0,0}, acc1 = {0,0,0,0};
    float4 accT0 = {0,0,0,0}, accT1 = {0,0,0,0};
    float z0=0.f, z1=0.f, dd0=0.f, dd1=0.f, sm0=0.f, sm1=0.f;
    __syncthreads();

    for (int cc = 0; cc < 4; cc++) {
        int j0 = tile*128 + cc*32;
        // Phase A: coalesced GMEM -> smem stage (32 tokens x 768 floats)
        const float4* gx = (const float4*)(tokens + (size_t)(b*N + j0)*DF);
        #pragma unroll 8
        for (int k = 0; k < 24; k++) {
            int idx = k*256 + tid;
            int t = idx / 192, f4 = idx - t*192;
            xs[t*193 + f4] = gx[idx];
        }
        __syncthreads();
        // Phase B: token-major partial dots (lane = token, warp covers 24 float4 of f)
        float dt0 = 0.f, dt1 = 0.f;
        {
            int fb = w*24;
            #pragma unroll
            for (int k = 0; k < 24; k++) {
                float4 x = xs[lane*193 + fb + k];
                float4 a = a0s[fb + k];
                float4 c = a1s[fb + k];
                dt0 += a.x*x.x + a.y*x.y + a.z*x.z + a.w*x.w;
                dt1 += c.x*x.x + c.y*x.y + c.z*x.z + c.w*x.w;
            }
        }
        dtp[w*32 + lane]       = dt0;
        dtp[256 + w*32 + lane] = dt1;
        __syncthreads();
        // Phase C: combine partials + sigmoid (all warps redundantly; lane = token)
        int j = j0 + lane;
        float d0 = 0.f, d1 = 0.f;
        #pragma unroll
        for (int ww = 0; ww < 8; ww++) {
            d0 += dtp[ww*32 + lane];
            d1 += dtp[256 + ww*32 + lane];
        }
        float s0 = g_s[(size_t)bk0*N + j], s1 = g_s[(size_t)bk1*N + j];
        float m  = g_mean[b*N + j];
        float p0 = 1.f/(1.f + __expf(-(SCALE*(s0*(d0 - m*sA0) + be0))));
        float p1 = 1.f/(1.f + __expf(-(SCALE*(s1*(d1 - m*sA1) + be1))));
        float at0 = p0 + EPS_SA, at1 = p1 + EPS_SA;
        float c0 = at0*s0, c1 = at1*s1;
        if (w == 0) {
            z0 += at0; z1 += at1; dd0 += c0*m; dd1 += c1*m;
            if (first) { sm0 += s0*m; sm1 += s1*m; }
            if (last) {
                float mk0 = masks[(size_t)bk0*N + j];
                float mk1 = masks[(size_t)bk1*N + j];
                out[OBJ_SIZE + (size_t)(bk0*2)*N + j]   = at0*mk0;
                out[OBJ_SIZE + (size_t)(bk0*2+1)*N + j] = (1.f - p0 + EPS_SA)*mk0;
                out[OBJ_SIZE + (size_t)(bk1*2)*N + j]   = at1*mk1;
                out[OBJ_SIZE + (size_t)(bk1*2+1)*N + j] = (1.f - p1 + EPS_SA)*mk1;
            }
        }
        // Phase D: f-major accumulate (thread owns one float4 column; shfl-broadcast weights)
        if (tid < 192) {
            if (first) {
                #pragma unroll
                for (int t = 0; t < 32; t++) {
                    float4 x = xs[t*193 + tid];
                    float c0t = __shfl_sync(0xffffffffu, c0, t);
                    float c1t = __shfl_sync(0xffffffffu, c1, t);
                    float s0t = __shfl_sync(0xffffffffu, s0, t);
                    float s1t = __shfl_sync(0xffffffffu, s1, t);
                    acc0.x += c0t*x.x;  acc0.y += c0t*x.y;  acc0.z += c0t*x.z;  acc0.w += c0t*x.w;
                    acc1.x += c1t*x.x;  acc1.y += c1t*x.y;  acc1.z += c1t*x.z;  acc1.w += c1t*x.w;
                    accT0.x += s0t*x.x; accT0.y += s0t*x.y; accT0.z += s0t*x.z; accT0.w += s0t*x.w;
                    accT1.x += s1t*x.x; accT1.y += s1t*x.y; accT1.z += s1t*x.z; accT1.w += s1t*x.w;
                }
            } else {
                #pragma unroll
                for (int t = 0; t < 32; t++) {
                    float4 x = xs[t*193 + tid];
                    float c0t = __shfl_sync(0xffffffffu, c0, t);
                    float c1t = __shfl_sync(0xffffffffu, c1, t);
                    acc0.x += c0t*x.x; acc0.y += c0t*x.y; acc0.z += c0t*x.z; acc0.w += c0t*x.w;
                    acc1.x += c1t*x.x; acc1.y += c1t*x.y; acc1.z += c1t*x.z; acc1.w += c1t*x.w;
                }
            }
        }
        __syncthreads();   // protect xs before next chunk's phase A
    }

    // epilogue: global accumulation
    if (tid < 192) {
        size_t f0 = (size_t)bk0*DF + tid*4;
        size_t f1 = (size_t)bk1*DF + tid*4;
        atomicAdd(&g_acc0[f0+0], acc0.x); atomicAdd(&g_acc0[f0+1], acc0.y);
        atomicAdd(&g_acc0[f0+2], acc0.z); atomicAdd(&g_acc0[f0+3], acc0.w);
        atomicAdd(&g_acc0[f1+0], acc1.x); atomicAdd(&g_acc0[f1+1], acc1.y);
        atomicAdd(&g_acc0[f1+2], acc1.z); atomicAdd(&g_acc0[f1+3], acc1.w);
        if (first) {
            atomicAdd(&g_T[f0+0], accT0.x); atomicAdd(&g_T[f0+1], accT0.y);
            atomicAdd(&g_T[f0+2], accT0.z); atomicAdd(&g_T[f0+3], accT0.w);
            atomicAdd(&g_T[f1+0], accT1.x); atomicAdd(&g_T[f1+1], accT1.y);
            atomicAdd(&g_T[f1+2], accT1.z); atomicAdd(&g_T[f1+3], accT1.w);
        }
    }
    if (w == 0) {
        warp_reduce2(z0, z1, lane);
        warp_reduce2(dd0, dd1, lane);
        if (first) warp_reduce2(sm0, sm1, lane);
        if (lane == 0) {
            atomicAdd(&g_z0[bk0], z0);  atomicAdd(&g_z0[bk1], z1);
            atomicAdd(&g_d0[bk0], dd0); atomicAdd(&g_d0[bk1], dd1);
            if (first) { atomicAdd(&g_sm[bk0], sm0); atomicAdd(&g_sm[bk1], sm1); }
        }
    }
}

// per slot row: reconstruct A/D/Z, updates -> GRU -> LN -> MLP.  grid NS blocks of 128
__global__ void upd_kernel(const float* __restrict__ ig,
                           const float* __restrict__ bih, const float* __restrict__ bhh,
                           const float* __restrict__ mg,  const float* __restrict__ mb,
                           const float* __restrict__ b1,  const float* __restrict__ b2,
                           float* __restrict__ out, int last) {
    __shared__ float gv[DF];
    __shared__ float su[DS], sh[DS], shh[DS];
    __shared__ float sy[4*DS];
    __shared__ float red[DS];
    int r = blockIdx.x, t = threadIdx.x;
    int bk = r >> 1, i = r & 1;
    const float ONE = 1.f + 2.f*EPS_SA;
    float Z0 = g_z0[bk], D0 = g_d0[bk];
    float Z = i ? (4096.f*ONE - Z0) : Z0;
    float D = i ? (g_sm[bk]*ONE - D0) : D0;
    for (int f = t; f < DF; f += DS) {
        float A = g_acc0[(size_t)bk*DF + f];
        if (i) A = g_T[(size_t)bk*DF + f]*ONE - A;
        gv[f] = ig[f] * (A - D);
    }
    float hprev = g_slots[r*DS + t];
    sh[t] = hprev;
    __syncthreads();
    {
        float a0=0.f,a1=0.f,a2=0.f,a3=0.f;
        #pragma unroll 4
        for (int f = 0; f < DF; f += 4) {
            a0 += g_WvT[(f+0)*DS + t] * gv[f+0];
            a1 += g_WvT[(f+1)*DS + t] * gv[f+1];
            a2 += g_WvT[(f+2)*DS + t] * gv[f+2];
            a3 += g_WvT[(f+3)*DS + t] * gv[f+3];
        }
        su[t] = ((a0+a1)+(a2+a3)) / Z + g_cv[t];
    }
    __syncthreads();
    // GRU (6 independent chains, coalesced transposed weights)
    float gi0 = bih[t], gi1 = bih[DS+t], gi2 = bih[2*DS+t];
    float gh0 = bhh[t], gh1 = bhh[DS+t], gh2 = bhh[2*DS+t];
    #pragma unroll 4
    for (int f = 0; f < DS; f++) {
        float uf = su[f], hf = sh[f];
        gi0 += g_WihT[f*(3*DS) + t]*uf;
        gi1 += g_WihT[f*(3*DS) + DS + t]*uf;
        gi2 += g_WihT[f*(3*DS) + 2*DS + t]*uf;
        gh0 += g_WhhT[f*(3*DS) + t]*hf;
        gh1 += g_WhhT[f*(3*DS) + DS + t]*hf;
        gh2 += g_WhhT[f*(3*DS) + 2*DS + t]*hf;
    }
    float rr = 1.f / (1.f + __expf(-(gi0 + gh0)));
    float zz = 1.f / (1.f + __expf(-(gi1 + gh1)));
    float nn = tanhf(gi2 + rr*gh2);
    float news = (1.f - zz)*nn + zz*hprev;
    // LN over 128 lanes
    red[t] = news; __syncthreads();
    #pragma unroll
    for (int h2 = 64; h2; h2 >>= 1) { if (t < h2) red[t] += red[t+h2]; __syncthreads(); }
    float m = red[0] * (1.f/DS); __syncthreads();
    float dv = news - m;
    red[t] = dv*dv; __syncthreads();
    #pragma unroll
    for (int h2 = 64; h2; h2 >>= 1) { if (t < h2) red[t] += red[t+h2]; __syncthreads(); }
    float rstd = rsqrtf(red[0]*(1.f/DS) + 1e-5f); __syncthreads();
    shh[t] = dv*rstd*mg[t] + mb[t];
    __syncthreads();
    // MLP (exact gelu)
    #pragma unroll
    for (int oo = 0; oo < 4; oo++) {
        int o = oo*DS + t;
        float a2 = b1[o];
        #pragma unroll 4
        for (int f = 0; f < DS; f++) a2 += g_W1T[f*(4*DS) + o]*shh[f];
        sy[o] = 0.5f * a2 * (1.f + erff(a2 * 0.70710678118654752f));
    }
    __syncthreads();
    {
        float a0=0.f,a1=0.f,a2=0.f,a3=0.f;
        #pragma unroll 4
        for (int o = 0; o < 4*DS; o += 4) {
            a0 += g_W2T[(o+0)*DS + t]*sy[o+0];
            a1 += g_W2T[(o+1)*DS + t]*sy[o+1];
            a2 += g_W2T[(o+2)*DS + t]*sy[o+2];
            a3 += g_W2T[(o+3)*DS + t]*sy[o+3];
        }
        float o2 = b2[t] + (a0+a1)+(a2+a3);
        g_slots[r*DS + t] = o2;
        if (last) out[r*DS + t] = o2;
    }
}

// ------------------- launch -------------------
#define BIG_SMEM (6560*16 + 2048)   // 107008 bytes

extern "C" void kernel_launch(void* const* d_in, const int* in_sizes, int n_in,
                              void* d_out, int out_size) {
    const float* tokens = (const float*)d_in[0];
    const float* pslots = (const float*)d_in[1];
    const float* masks  = (const float*)d_in[2];
    const float* eps    = (const float*)d_in[3];
    const float* ig     = (const float*)d_in[4];
    const float* ib     = (const float*)d_in[5];
    const float* sg     = (const float*)d_in[6];
    const float* sb     = (const float*)d_in[7];
    const float* Wq     = (const float*)d_in[8];
    const float* Wk     = (const float*)d_in[9];
    const float* Wv     = (const float*)d_in[10];
    const float* Wih    = (const float*)d_in[11];
    const float* Whh    = (const float*)d_in[12];
    const float* bih    = (const float*)d_in[13];
    const float* bhh    = (const float*)d_in[14];
    const float* mg     = (const float*)d_in[15];
    const float* mb     = (const float*)d_in[16];
    const float* W1     = (const float*)d_in[17];
    const float* b1     = (const float*)d_in[18];
    const float* W2     = (const float*)d_in[19];
    const float* b2     = (const float*)d_in[20];
    float* out = (float*)d_out;

    cudaFuncSetAttribute(big_kernel, cudaFuncAttributeMaxDynamicSharedMemorySize, BIG_SMEM);

    // launch index 3 (profiled) = first big_kernel
    stats_kernel<<<B*N/8, 256>>>(tokens);                               // 0
    dss_kernel<<<BK, 256>>>(masks);                                     // 1
    qa_kernel<<<BK, 256>>>(pslots, eps, Wq, Wk, sg, sb, ig, ib, 1);     // 2
    big_kernel<<<32*32, 256, BIG_SMEM>>>(tokens, masks, out, 1, 0);     // 3 (profiled)
    tr_kernel<<<(DF*DS + 2*DS*3*DS + 2*DS*4*DS + 255)/256, 256>>>(Wv, Wih, Whh, W1, W2); // 4
    cv_kernel<<<1, DS>>>(ib);                                           // 5
    upd_kernel<<<NS, DS>>>(ig, bih, bhh, mg, mb, b1, b2, out, 0);       // 6

    for (int it = 1; it < 3; it++) {
        int last = (it == 2);
        qa_kernel<<<BK, 256>>>(pslots, eps, Wq, Wk, sg, sb, ig, ib, 0);
        big_kernel<<<32*32, 256, BIG_SMEM>>>(tokens, masks, out, 0, last);
        upd_kernel<<<NS, DS>>>(ig, bih, bhh, mg, mb, b1, b2, out, last);
    }
}

// round 10
// speedup vs baseline: 2.1312x; 1.7722x over previous
#include <cuda_runtime.h>
#include <math.h>

#define B 8
#define N 4096
#define DF 768
#define K1 8
#define K2 2
#define DS 128
#define BK (B*K1)        // 64
#define NS (BK*K2)       // 128 slot rows
#define SCALE 0.088388347648318447f
#define EPS_SA 1e-8f
#define OBJ_SIZE (NS*DS)

// ------------------- scratch (device globals) -------------------
__device__ float g_mean[B*N];
__device__ float g_var[B*N];
__device__ float g_s[BK*N];
__device__ float g_sm[BK];                       // sum_j s_j * m_j per bk
__device__ __align__(16) float g_T[BK*DF];       // sum_j s_j * x_j per bk
__device__ float g_slots[NS*DS];
__device__ __align__(16) float g_aD[BK*DF];      // delta a-vector per bk
__device__ float g_sAD[BK];
__device__ float g_beD[BK];
__device__ __align__(16) float g_acc0[BK*DF];    // slot-0 accumulator
__device__ float g_z0[BK];
__device__ float g_d0[BK];
__device__ float g_cv[DS];
// transposed weights
__device__ float g_WvT[DF*DS];
__device__ float g_WihT[DS*3*DS];
__device__ float g_WhhT[DS*3*DS];
__device__ float g_W1T[DS*4*DS];
__device__ float g_W2T[4*DS*DS];

// paired warp reduction: on exit all lanes hold x=sum(x), y=sum(y).
__device__ __forceinline__ void warp_reduce2(float& x, float& y, int lane) {
    float xo = __shfl_xor_sync(0xffffffffu, x, 16);
    float yo = __shfl_xor_sync(0xffffffffu, y, 16);
    float v  = (lane < 16) ? (x + xo) : (y + yo);
    #pragma unroll
    for (int off = 8; off; off >>= 1) v += __shfl_xor_sync(0xffffffffu, v, off);
    x = __shfl_sync(0xffffffffu, v, 0);
    y = __shfl_sync(0xffffffffu, v, 16);
}

__device__ __forceinline__ float block_reduce_256(float v, float* red, int tid) {
    red[tid] = v; __syncthreads();
    #pragma unroll
    for (int h = 128; h > 0; h >>= 1) {
        if (tid < h) red[tid] += red[tid + h];
        __syncthreads();
    }
    float r = red[0];
    __syncthreads();
    return r;
}

// ------------------- one-time kernels -------------------
// per-token mean/var over DF.  grid B*N/8 blocks of 256 (warp/row)
__global__ void stats_kernel(const float* __restrict__ tokens) {
    int row  = blockIdx.x * 8 + (threadIdx.x >> 5);
    int lane = threadIdx.x & 31;
    const float4* xp = (const float4*)(tokens + (size_t)row * DF);
    float s = 0.f, s2 = 0.f;
    #pragma unroll
    for (int k = 0; k < 6; k++) {
        float4 v = xp[k*32 + lane];
        s  += v.x + v.y + v.z + v.w;
        s2 += v.x*v.x + v.y*v.y + v.z*v.z + v.w*v.w;
    }
    #pragma unroll
    for (int off = 16; off; off >>= 1) {
        s  += __shfl_xor_sync(0xffffffffu, s,  off);
        s2 += __shfl_xor_sync(0xffffffffu, s2, off);
    }
    if (lane == 0) {
        float m = s * (1.f/DF);
        g_mean[row] = m;
        g_var[row]  = s2 * (1.f/DF) - m*m;
    }
}

// fused denom + s.  grid BK blocks of 256
__global__ void dss_kernel(const float* __restrict__ masks) {
    __shared__ float red[256];
    int bk = blockIdx.x, b = bk >> 3, tid = threadIdx.x;
    float s = 0.f;
    for (int j = tid; j < N; j += 256) s += masks[(size_t)bk*N + j];
    float denom = block_reduce_256(s, red, tid) * (1.f/N);
    int good = denom > 1e-6f;
    float inv = 1.f / (denom + 1e-6f);
    for (int j = tid; j < N; j += 256) {
        float w = good ? masks[(size_t)bk*N + j] * inv : 1.0f;
        float v = g_var[b*N + j];
        g_s[(size_t)bk*N + j] = w * rsqrtf(w*w*v + 1e-5f);
    }
}

// transpose weight matrices (Wv, Wih, Whh, W1, W2)
__global__ void tr_kernel(const float* __restrict__ Wv,
                          const float* __restrict__ Wih, const float* __restrict__ Whh,
                          const float* __restrict__ W1, const float* __restrict__ W2) {
    int i = blockIdx.x*256 + threadIdx.x;
    if (i < DF*DS) { int f = i/DS, o = i%DS; g_WvT[i] = Wv[o*DF + f]; return; }
    i -= DF*DS;
    if (i < DS*3*DS) { int f = i/(3*DS), o = i%(3*DS); g_WihT[i] = Wih[o*DS + f]; return; }
    i -= DS*3*DS;
    if (i < DS*3*DS) { int f = i/(3*DS), o = i%(3*DS); g_WhhT[i] = Whh[o*DS + f]; return; }
    i -= DS*3*DS;
    if (i < DS*4*DS) { int f = i/(4*DS), o = i%(4*DS); g_W1T[i] = W1[o*DS + f]; return; }
    i -= DS*4*DS;
    if (i < 4*DS*DS) { int o = i/DS, t = i%DS; g_W2T[i] = W2[t*4*DS + o]; return; }
}

// cv = Wv @ ln_in_b.  grid 16 blocks x 256 (warp per output col)
__global__ void cv_kernel(const float* __restrict__ Wv, const float* __restrict__ lnb) {
    int col  = blockIdx.x*8 + (threadIdx.x >> 5);
    int lane = threadIdx.x & 31;
    float a = 0.f;
    #pragma unroll
    for (int k = 0; k < 24; k++) {
        int f = k*32 + lane;
        a += Wv[(size_t)col*DF + f] * lnb[f];
    }
    #pragma unroll
    for (int off = 16; off; off >>= 1) a += __shfl_xor_sync(0xffffffffu, a, off);
    if (lane == 0) g_cv[col] = a;
}

// ------------------- per-iteration kernels -------------------
// per bk: (opt) init slots, LN both slots, qDelta, aDelta; zero accumulators.
__global__ void qa_kernel(const float* __restrict__ ps, const float* __restrict__ eps,
                          const float* __restrict__ Wq, const float* __restrict__ Wk,
                          const float* __restrict__ sg, const float* __restrict__ sb,
                          const float* __restrict__ ig, const float* __restrict__ ib,
                          int first) {
    __shared__ float sn[2][DS], qsh[2][DS], qD[DS], red[256];
    int bk = blockIdx.x, tid = threadIdx.x;
    int half = tid >> 7, t = tid & 127;
    int r = bk*2 + half;
    float val;
    if (first) {
        val = ps[bk*DS + t] + 0.01f * eps[r*DS + t];
        g_slots[r*DS + t] = val;
    } else {
        val = g_slots[r*DS + t];
    }
    // segmented mean/var per half
    red[tid] = val; __syncthreads();
    #pragma unroll
    for (int h = 64; h; h >>= 1) { if (t < h) red[tid] += red[tid + h]; __syncthreads(); }
    float m = red[half*128] * (1.f/DS);
    __syncthreads();
    float dv = val - m;
    red[tid] = dv*dv; __syncthreads();
    #pragma unroll
    for (int h = 64; h; h >>= 1) { if (t < h) red[tid] += red[tid + h]; __syncthreads(); }
    float rstd = rsqrtf(red[half*128] * (1.f/DS) + 1e-5f);
    __syncthreads();
    sn[half][t] = dv * rstd * sg[t] + sb[t];
    __syncthreads();
    {   // q = sn @ Wq^T
        float q0 = 0.f, q1 = 0.f;
        #pragma unroll 4
        for (int f = 0; f < DS; f += 2) {
            q0 += Wq[t*DS + f]   * sn[half][f];
            q1 += Wq[t*DS + f+1] * sn[half][f+1];
        }
        qsh[half][t] = q0 + q1;
    }
    __syncthreads();
    if (tid < DS) qD[tid] = qsh[0][tid] - qsh[1][tid];
    __syncthreads();
    float psum = 0.f, pbeta = 0.f;
    #pragma unroll
    for (int ff = 0; ff < 3; ff++) {
        int f = ff*256 + tid;
        float r0 = 0.f, r1 = 0.f;
        #pragma unroll 4
        for (int c = 0; c < DS; c += 2) {
            r0 += Wk[c*DF + f]     * qD[c];
            r1 += Wk[(c+1)*DF + f] * qD[c+1];
        }
        float raw = r0 + r1;
        float a = raw * ig[f];
        g_aD[(size_t)bk*DF + f]   = a;
        g_acc0[(size_t)bk*DF + f] = 0.f;
        if (first) g_T[(size_t)bk*DF + f] = 0.f;
        psum  += a;
        pbeta += raw * ib[f];
    }
    float tsum  = block_reduce_256(psum, red, tid);
    float tbeta = block_reduce_256(pbeta, red, tid);
    if (tid == 0) {
        g_sAD[bk] = tsum; g_beD[bk] = tbeta;
        g_z0[bk] = 0.f; g_d0[bk] = 0.f;
        if (first) g_sm[bk] = 0.f;
    }
}

// Phased big kernel v2: dots computed during staging (no phase B re-read).
// block = 256 thr (8 warps), pair of bks, 128 tokens in 4 chunks of 32.
// Each warp owns 4 tokens per chunk; a-vectors live in registers.
__global__ void __launch_bounds__(256) big_kernel(const float* __restrict__ tokens,
                                                  const float* __restrict__ masks,
                                                  float* __restrict__ out,
                                                  int first, int last) {
    extern __shared__ float4 sm4[];
    float4* xs  = sm4;                   // 32*193 = 6176 float4
    float*  dtp = (float*)(sm4 + 6176);  // 64 floats

    int p = blockIdx.x & 31, tile = blockIdx.x >> 5;
    int bk0 = 2*p, bk1 = bk0 + 1, b = p >> 2;
    int tid = threadIdx.x, w = tid >> 5, lane = tid & 31;

    // a-vectors in registers: lane covers f4 = lane + 32k, k<6
    const float4* a0p = (const float4*)(g_aD + (size_t)bk0*DF);
    const float4* a1p = (const float4*)(g_aD + (size_t)bk1*DF);
    float4 a0v[6], a1v[6];
    #pragma unroll
    for (int k = 0; k < 6; k++) {
        a0v[k] = a0p[k*32 + lane];
        a1v[k] = a1p[k*32 + lane];
    }
    float sA0 = g_sAD[bk0], sA1 = g_sAD[bk1];
    float be0 = g_beD[bk0], be1 = g_beD[bk1];
    float4 acc0 = {0,0,0,0}, acc1 = {0,0,0,0};
    float4 accT0 = {0,0,0,0}, accT1 = {0,0,0,0};
    float z0=0.f, z1=0.f, dd0=0.f, dd1=0.f, sm0=0.f, sm1=0.f;

    for (int cc = 0; cc < 4; cc++) {
        int j0 = tile*128 + cc*32;
        // Phase A: warp w stages tokens w*4..w*4+3 AND computes their delta-dots
        #pragma unroll
        for (int u = 0; u < 4; u++) {
            int t = w*4 + u;
            const float4* gx = (const float4*)(tokens + (size_t)(b*N + j0 + t)*DF);
            float d0 = 0.f, d1 = 0.f;
            #pragma unroll
            for (int k = 0; k < 6; k++) {
                float4 x = gx[k*32 + lane];
                xs[t*193 + k*32 + lane] = x;
                d0 += a0v[k].x*x.x + a0v[k].y*x.y + a0v[k].z*x.z + a0v[k].w*x.w;
                d1 += a1v[k].x*x.x + a1v[k].y*x.y + a1v[k].z*x.z + a1v[k].w*x.w;
            }
            warp_reduce2(d0, d1, lane);
            if (lane == 0) { dtp[t] = d0; dtp[32 + t] = d1; }
        }
        __syncthreads();
        // Phase C: sigmoid weights (all warps redundantly; lane = token)
        int j = j0 + lane;
        float d0 = dtp[lane], d1 = dtp[32 + lane];
        float s0 = g_s[(size_t)bk0*N + j], s1 = g_s[(size_t)bk1*N + j];
        float m  = g_mean[b*N + j];
        float p0 = 1.f/(1.f + __expf(-(SCALE*(s0*(d0 - m*sA0) + be0))));
        float p1 = 1.f/(1.f + __expf(-(SCALE*(s1*(d1 - m*sA1) + be1))));
        float at0 = p0 + EPS_SA, at1 = p1 + EPS_SA;
        float c0 = at0*s0, c1 = at1*s1;
        if (w == 0) {
            z0 += at0; z1 += at1; dd0 += c0*m; dd1 += c1*m;
            if (first) { sm0 += s0*m; sm1 += s1*m; }
            if (last) {
                float mk0 = masks[(size_t)bk0*N + j];
                float mk1 = masks[(size_t)bk1*N + j];
                out[OBJ_SIZE + (size_t)(bk0*2)*N + j]   = at0*mk0;
                out[OBJ_SIZE + (size_t)(bk0*2+1)*N + j] = (1.f - p0 + EPS_SA)*mk0;
                out[OBJ_SIZE + (size_t)(bk1*2)*N + j]   = at1*mk1;
                out[OBJ_SIZE + (size_t)(bk1*2+1)*N + j] = (1.f - p1 + EPS_SA)*mk1;
            }
        }
        // Phase D: f-major accumulate (thread owns one float4 column; shfl weights)
        if (tid < 192) {
            if (first) {
                #pragma unroll
                for (int t = 0; t < 32; t++) {
                    float4 x = xs[t*193 + tid];
                    float c0t = __shfl_sync(0xffffffffu, c0, t);
                    float c1t = __shfl_sync(0xffffffffu, c1, t);
                    float s0t = __shfl_sync(0xffffffffu, s0, t);
                    float s1t = __shfl_sync(0xffffffffu, s1, t);
                    acc0.x += c0t*x.x;  acc0.y += c0t*x.y;  acc0.z += c0t*x.z;  acc0.w += c0t*x.w;
                    acc1.x += c1t*x.x;  acc1.y += c1t*x.y;  acc1.z += c1t*x.z;  acc1.w += c1t*x.w;
                    accT0.x += s0t*x.x; accT0.y += s0t*x.y; accT0.z += s0t*x.z; accT0.w += s0t*x.w;
                    accT1.x += s1t*x.x; accT1.y += s1t*x.y; accT1.z += s1t*x.z; accT1.w += s1t*x.w;
                }
            } else {
                #pragma unroll
                for (int t = 0; t < 32; t++) {
                    float4 x = xs[t*193 + tid];
                    float c0t = __shfl_sync(0xffffffffu, c0, t);
                    float c1t = __shfl_sync(0xffffffffu, c1, t);
                    acc0.x += c0t*x.x; acc0.y += c0t*x.y; acc0.z += c0t*x.z; acc0.w += c0t*x.w;
                    acc1.x += c1t*x.x; acc1.y += c1t*x.y; acc1.z += c1t*x.z; acc1.w += c1t*x.w;
                }
            }
        }
        __syncthreads();   // protect xs & dtp before next chunk
    }

    // epilogue: global accumulation
    if (tid < 192) {
        size_t f0 = (size_t)bk0*DF + tid*4;
        size_t f1 = (size_t)bk1*DF + tid*4;
        atomicAdd(&g_acc0[f0+0], acc0.x); atomicAdd(&g_acc0[f0+1], acc0.y);
        atomicAdd(&g_acc0[f0+2], acc0.z); atomicAdd(&g_acc0[f0+3], acc0.w);
        atomicAdd(&g_acc0[f1+0], acc1.x); atomicAdd(&g_acc0[f1+1], acc1.y);
        atomicAdd(&g_acc0[f1+2], acc1.z); atomicAdd(&g_acc0[f1+3], acc1.w);
        if (first) {
            atomicAdd(&g_T[f0+0], accT0.x); atomicAdd(&g_T[f0+1], accT0.y);
            atomicAdd(&g_T[f0+2], accT0.z); atomicAdd(&g_T[f0+3], accT0.w);
            atomicAdd(&g_T[f1+0], accT1.x); atomicAdd(&g_T[f1+1], accT1.y);
            atomicAdd(&g_T[f1+2], accT1.z); atomicAdd(&g_T[f1+3], accT1.w);
        }
    }
    if (w == 0) {
        warp_reduce2(z0, z1, lane);
        warp_reduce2(dd0, dd1, lane);
        if (first) warp_reduce2(sm0, sm1, lane);
        if (lane == 0) {
            atomicAdd(&g_z0[bk0], z0);  atomicAdd(&g_z0[bk1], z1);
            atomicAdd(&g_d0[bk0], dd0); atomicAdd(&g_d0[bk1], dd1);
            if (first) { atomicAdd(&g_sm[bk0], sm0); atomicAdd(&g_sm[bk1], sm1); }
        }
    }
}

// upd v2: 256 threads per slot row; f-split halves double warps & halve chains.
__global__ void __launch_bounds__(256) upd_kernel(const float* __restrict__ ig,
                           const float* __restrict__ bih, const float* __restrict__ bhh,
                           const float* __restrict__ mg,  const float* __restrict__ mb,
                           const float* __restrict__ b1,  const float* __restrict__ b2,
                           float* __restrict__ out, int last) {
    __shared__ float gv[DF];
    __shared__ float su[DS], sh[DS], shh[DS], snews[DS];
    __shared__ float sy[4*DS];
    __shared__ float part[6][2][DS];
    __shared__ float red[DS];
    int r = blockIdx.x, tid = threadIdx.x;
    int col = tid & 127, half = tid >> 7;
    int bk = r >> 1, i = r & 1;
    const float ONE = 1.f + 2.f*EPS_SA;
    float Z0 = g_z0[bk], D0 = g_d0[bk];
    float Z = i ? (4096.f*ONE - Z0) : Z0;
    float D = i ? (g_sm[bk]*ONE - D0) : D0;
    for (int f = tid; f < DF; f += 256) {
        float A = g_acc0[(size_t)bk*DF + f];
        if (i) A = g_T[(size_t)bk*DF + f]*ONE - A;
        gv[f] = ig[f] * (A - D);
    }
    if (tid < DS) sh[tid] = g_slots[r*DS + tid];
    __syncthreads();
    // Wv matvec: halves split the 768 f-range
    {
        float a0=0.f,a1=0.f,a2=0.f,a3=0.f;
        int f0 = half*384;
        #pragma unroll 8
        for (int f = f0; f < f0+384; f += 4) {
            a0 += g_WvT[(f+0)*DS + col] * gv[f+0];
            a1 += g_WvT[(f+1)*DS + col] * gv[f+1];
            a2 += g_WvT[(f+2)*DS + col] * gv[f+2];
            a3 += g_WvT[(f+3)*DS + col] * gv[f+3];
        }
        part[0][half][col] = (a0+a1)+(a2+a3);
    }
    __syncthreads();
    if (tid < DS) su[tid] = (part[0][0][tid] + part[0][1][tid]) / Z + g_cv[tid];
    __syncthreads();
    // GRU: halves split the 128 f-range (64 each), 6 accumulators
    {
        float gi0=0.f, gi1=0.f, gi2=0.f, gh0=0.f, gh1=0.f, gh2=0.f;
        int f0 = half*64;
        #pragma unroll 4
        for (int f = f0; f < f0+64; f++) {
            float uf = su[f], hf = sh[f];
            gi0 += g_WihT[f*(3*DS) + col]*uf;
            gi1 += g_WihT[f*(3*DS) + DS + col]*uf;
            gi2 += g_WihT[f*(3*DS) + 2*DS + col]*uf;
            gh0 += g_WhhT[f*(3*DS) + col]*hf;
            gh1 += g_WhhT[f*(3*DS) + DS + col]*hf;
            gh2 += g_WhhT[f*(3*DS) + 2*DS + col]*hf;
        }
        part[0][half][col] = gi0; part[1][half][col] = gi1; part[2][half][col] = gi2;
        part[3][half][col] = gh0; part[4][half][col] = gh1; part[5][half][col] = gh2;
    }
    __syncthreads();
    if (tid < DS) {
        int t = tid;
        float gi0 = bih[t]        + part[0][0][t] + part[0][1][t];
        float gi1 = bih[DS+t]     + part[1][0][t] + part[1][1][t];
        float gi2 = bih[2*DS+t]   + part[2][0][t] + part[2][1][t];
        float gh0 = bhh[t]        + part[3][0][t] + part[3][1][t];
        float gh1 = bhh[DS+t]     + part[4][0][t] + part[4][1][t];
        float gh2 = bhh[2*DS+t]   + part[5][0][t] + part[5][1][t];
        float rr = 1.f / (1.f + __expf(-(gi0 + gh0)));
        float zz = 1.f / (1.f + __expf(-(gi1 + gh1)));
        float nn = tanhf(gi2 + rr*gh2);
        snews[t] = (1.f - zz)*nn + zz*sh[t];
    }
    __syncthreads();
    // LN over the 128 news values
    if (tid < DS) red[tid] = snews[tid];
    __syncthreads();
    #pragma unroll
    for (int h2 = 64; h2; h2 >>= 1) { if (tid < h2) red[tid] += red[tid+h2]; __syncthreads(); }
    float m = red[0] * (1.f/DS);
    __syncthreads();
    if (tid < DS) { float dv = snews[tid] - m; red[tid] = dv*dv; }
    __syncthreads();
    #pragma unroll
    for (int h2 = 64; h2; h2 >>= 1) { if (tid < h2) red[tid] += red[tid+h2]; __syncthreads(); }
    float rstd = rsqrtf(red[0]*(1.f/DS) + 1e-5f);
    __syncthreads();
    if (tid < DS) shh[tid] = (snews[tid] - m)*rstd*mg[tid] + mb[tid];
    __syncthreads();
    // MLP W1: each thread computes outputs tid and tid+256 (two independent chains)
    {
        float aa = b1[tid], ab = b1[tid+256];
        #pragma unroll 4
        for (int f = 0; f < DS; f++) {
            float s = shh[f];
            aa += g_W1T[f*(4*DS) + tid]       * s;
            ab += g_W1T[f*(4*DS) + tid + 256] * s;
        }
        sy[tid]       = 0.5f * aa * (1.f + erff(aa * 0.70710678118654752f));
        sy[tid + 256] = 0.5f * ab * (1.f + erff(ab * 0.70710678118654752f));
    }
    __syncthreads();
    // W2: halves split the 512 o-range
    {
        float a0=0.f,a1=0.f,a2=0.f,a3=0.f;
        int o0 = half*256;
        #pragma unroll 8
        for (int o = o0; o < o0+256; o += 4) {
            a0 += g_W2T[(o+0)*DS + col]*sy[o+0];
            a1 += g_W2T[(o+1)*DS + col]*sy[o+1];
            a2 += g_W2T[(o+2)*DS + col]*sy[o+2];
            a3 += g_W2T[(o+3)*DS + col]*sy[o+3];
        }
        part[0][half][col] = (a0+a1)+(a2+a3);
    }
    __syncthreads();
    if (tid < DS) {
        float o2 = b2[tid] + part[0][0][tid] + part[0][1][tid];
        g_slots[r*DS + tid] = o2;
        if (last) out[r*DS + tid] = o2;
    }
}

// ------------------- launch -------------------
#define BIG_SMEM (6176*16 + 256)   // 99072 bytes

extern "C" void kernel_launch(void* const* d_in, const int* in_sizes, int n_in,
                              void* d_out, int out_size) {
    const float* tokens = (const float*)d_in[0];
    const float* pslots = (const float*)d_in[1];
    const float* masks  = (const float*)d_in[2];
    const float* eps    = (const float*)d_in[3];
    const float* ig     = (const float*)d_in[4];
    const float* ib     = (const float*)d_in[5];
    const float* sg     = (const float*)d_in[6];
    const float* sb     = (const float*)d_in[7];
    const float* Wq     = (const float*)d_in[8];
    const float* Wk     = (const float*)d_in[9];
    const float* Wv     = (const float*)d_in[10];
    const float* Wih    = (const float*)d_in[11];
    const float* Whh    = (const float*)d_in[12];
    const float* bih    = (const float*)d_in[13];
    const float* bhh    = (const float*)d_in[14];
    const float* mg     = (const float*)d_in[15];
    const float* mb     = (const float*)d_in[16];
    const float* W1     = (const float*)d_in[17];
    const float* b1     = (const float*)d_in[18];
    const float* W2     = (const float*)d_in[19];
    const float* b2     = (const float*)d_in[20];
    float* out = (float*)d_out;

    cudaFuncSetAttribute(big_kernel, cudaFuncAttributeMaxDynamicSharedMemorySize, BIG_SMEM);

    // launch index 3 (profiled) = first big_kernel
    stats_kernel<<<B*N/8, 256>>>(tokens);                               // 0
    dss_kernel<<<BK, 256>>>(masks);                                     // 1
    qa_kernel<<<BK, 256>>>(pslots, eps, Wq, Wk, sg, sb, ig, ib, 1);     // 2
    big_kernel<<<32*32, 256, BIG_SMEM>>>(tokens, masks, out, 1, 0);     // 3 (profiled)
    tr_kernel<<<(DF*DS + 2*DS*3*DS + 2*DS*4*DS + 255)/256, 256>>>(Wv, Wih, Whh, W1, W2); // 4
    cv_kernel<<<16, 256>>>(Wv, ib);                                     // 5
    upd_kernel<<<NS, 256>>>(ig, bih, bhh, mg, mb, b1, b2, out, 0);      // 6

    for (int it = 1; it < 3; it++) {
        int last = (it == 2);
        qa_kernel<<<BK, 256>>>(pslots, eps, Wq, Wk, sg, sb, ig, ib, 0);
        big_kernel<<<32*32, 256, BIG_SMEM>>>(tokens, masks, out, 0, last);
        upd_kernel<<<NS, 256>>>(ig, bih, bhh, mg, mb, b1, b2, out, last);
    }
}